// round 15
// baseline (speedup 1.0000x reference)
#include <cuda_runtime.h>
#include <cuda_bf16.h>
#include <cstdint>
#include <math.h>

#define B_    32
#define T_    512
#define D_    300
#define U_    300
#define NG_   1200       // 4*U
#define ZPAD  1216       // padded zx row stride
#define M_    16384      // B*T

// ---- clustered recurrence tiling (r9/r14 compute config) ----
#define CL    8          // CTAs per cluster (unit groups)
#define NUc   38         // units per CTA (8*38=304, last 4 masked)
#define NCOLc 152        // 4*NUc gate columns per CTA
#define BGc   4          // batches per CTA
#define KCHc  4          // k chunks
#define KPc   38         // k-pairs per chunk (4*76 = 304 padded k)
#define HPAD  154        // hh row length in ULL pairs (152 used + pad)
#define RTc   608        // threads = KCHc * NCOLc exactly
#define CSTEPS 128       // steps per chunk launch (4 chunks x 128 = 512)
#define SLICE_BYTES 608u // 152 pushed f32 per source slice

typedef unsigned long long ULL;

// ------------------- static device scratch (no allocs allowed) -------------
__device__ __align__(16) float g_zx[2][M_][ZPAD];     // x@Wk+b per dir
__device__ __align__(16) float g_hs[2][B_][T_][U_];   // h history per dir
__device__ __align__(16) float g_hcur[2][B_][U_];     // h carried across chunks
__device__ __align__(16) float g_ccur[2][B_][U_];     // c carried across chunks

// ------------------- helpers ----------------------------------------------
union UF2 { float2 f; ULL u; };
__device__ __forceinline__ ULL pack2(float a, float b) {
    UF2 x; x.f = make_float2(a, b); return x.u;
}
__device__ __forceinline__ float2 unpack2(ULL v) {
    UF2 x; x.u = v; return x.f;
}
__device__ __forceinline__ void ffma2(ULL& d, ULL a, ULL b) {
    asm("fma.rn.f32x2 %0, %1, %2, %0;" : "+l"(d) : "l"(a), "l"(b));
}
__device__ __forceinline__ float sigm_f(float x) {
    return __fdividef(1.f, 1.f + __expf(-x));
}
__device__ __forceinline__ float tanh_f(float x) {
    float e = __expf(2.f * fabsf(x));
    float t = 1.f - __fdividef(2.f, e + 1.f);
    return copysignf(t, x);
}
__device__ __forceinline__ uint32_t smem_u32(const void* p) {
    uint32_t a;
    asm("{ .reg .u64 t; cvta.to.shared.u64 t, %1; cvt.u32.u64 %0, t; }" : "=r"(a) : "l"(p));
    return a;
}
// store+remote-mbar-completion in one message (no fences needed)
__device__ __forceinline__ void st_async_f32(uint32_t laddr, uint32_t lmbar, int rank, float v) {
    uint32_t ra, rm;
    asm volatile("mapa.shared::cluster.u32 %0, %1, %2;" : "=r"(ra) : "r"(laddr), "r"(rank));
    asm volatile("mapa.shared::cluster.u32 %0, %1, %2;" : "=r"(rm) : "r"(lmbar), "r"(rank));
    asm volatile("st.async.weak.shared::cluster.mbarrier::complete_tx::bytes.u32 [%0], %1, [%2];"
                 :: "r"(ra), "r"(__float_as_uint(v)), "r"(rm) : "memory");
}
__device__ __forceinline__ void mbar_init(uint32_t mbar, uint32_t cnt) {
    asm volatile("mbarrier.init.shared.b64 [%0], %1;" :: "r"(mbar), "r"(cnt) : "memory");
}
__device__ __forceinline__ void mbar_arm(uint32_t mbar, uint32_t txb) {
    asm volatile("mbarrier.arrive.expect_tx.shared.b64 _, [%0], %1;" :: "r"(mbar), "r"(txb) : "memory");
}
__device__ __forceinline__ void mbar_wait(uint32_t mbar, uint32_t parity) {
    asm volatile(
        "{\n\t.reg .pred P;\n\t"
        "W_%=:\n\t"
        "mbarrier.try_wait.parity.acquire.cta.shared::cta.b64 P, [%0], %1, 0x989680;\n\t"
        "@!P bra W_%=;\n\t}"
        :: "r"(mbar), "r"(parity) : "memory");
}
__device__ __forceinline__ void cluster_sync_() {
    asm volatile("barrier.cluster.arrive.aligned;" ::: "memory");
    asm volatile("barrier.cluster.wait.aligned;" ::: "memory");
}

// ------------------- kernel 0: zero carried state --------------------------
__global__ void init_state() {
    int i = blockIdx.x * blockDim.x + threadIdx.x;
    if (i < 2 * B_ * U_) {
        ((float*)g_hcur)[i] = 0.f;
        ((float*)g_ccur)[i] = 0.f;
    }
}

// ------------------- kernel 1: zx = gather(emb) @ Wk + b -------------------
#define GKT 19   // ceil(304/16)

__global__ void __launch_bounds__(256, 2) gemm_zx(const int* __restrict__ idx,
                                                  const float* __restrict__ WkF,
                                                  const float* __restrict__ WkB,
                                                  const float* __restrict__ bF,
                                                  const float* __restrict__ bB,
                                                  const float* __restrict__ emb) {
    const int dir = blockIdx.z;
    const float* __restrict__ Wk   = dir ? WkB : WkF;
    const float* __restrict__ bias = dir ? bB  : bF;
    const int m0 = blockIdx.x * 128;
    const int n0 = blockIdx.y * 64;
    const int tid = threadIdx.x;

    __shared__ ULL A_s[2][128][9];
    __shared__ ULL B_s[2][64][9];
    __shared__ int row_s[128];

    if (tid < 128) row_s[tid] = idx[m0 + tid];
    __syncthreads();

    const int mt = tid >> 4;
    const int nt = tid & 15;

    ULL acc[8][4];
#pragma unroll
    for (int i = 0; i < 8; i++)
#pragma unroll
        for (int j = 0; j < 4; j++) acc[i][j] = 0ULL;

    ULL aReg[4];
    ULL bReg[2];

    auto grab = [&](int kt) {
#pragma unroll
        for (int l = 0; l < 4; l++) {
            int id = tid + 256 * l;
            int m  = id >> 3;
            int kp = id & 7;
            int k0 = kt * 16 + kp * 2;
            if (k0 < D_) {
                const float* ep = emb + (size_t)row_s[m] * D_ + k0;
                float2 v = *(const float2*)ep;
                aReg[l] = pack2(v.x, v.y);
            } else aReg[l] = 0ULL;
        }
#pragma unroll
        for (int l = 0; l < 2; l++) {
            int id = tid + 256 * l;
            int n  = id & 63;
            int kp = id >> 6;
            int k0 = kt * 16 + kp * 2;
            int gn = n0 + n;
            if (k0 < D_ && gn < NG_) {
                float v0 = Wk[(size_t)k0 * NG_ + gn];
                float v1 = Wk[(size_t)(k0 + 1) * NG_ + gn];
                bReg[l] = pack2(v0, v1);
            } else bReg[l] = 0ULL;
        }
    };
    auto commit = [&](int st) {
#pragma unroll
        for (int l = 0; l < 4; l++) {
            int id = tid + 256 * l;
            A_s[st][id >> 3][id & 7] = aReg[l];
        }
#pragma unroll
        for (int l = 0; l < 2; l++) {
            int id = tid + 256 * l;
            B_s[st][id & 63][id >> 6] = bReg[l];
        }
    };

    grab(0); commit(0);
    __syncthreads();

    for (int kt = 0; kt < GKT; kt++) {
        const int st = kt & 1;
        if (kt + 1 < GKT) grab(kt + 1);

#pragma unroll
        for (int kp = 0; kp < 8; kp++) {
            ULL a2[8], b2[4];
#pragma unroll
            for (int i = 0; i < 8; i++) a2[i] = A_s[st][mt + 16 * i][kp];
#pragma unroll
            for (int j = 0; j < 4; j++) b2[j] = B_s[st][nt + 16 * j][kp];
#pragma unroll
            for (int i = 0; i < 8; i++)
#pragma unroll
                for (int j = 0; j < 4; j++) ffma2(acc[i][j], a2[i], b2[j]);
        }

        if (kt + 1 < GKT) commit((kt + 1) & 1);
        __syncthreads();
    }

#pragma unroll
    for (int i = 0; i < 8; i++) {
        int m = m0 + mt + 16 * i;
        float* orow = &g_zx[dir][m][0];
#pragma unroll
        for (int j = 0; j < 4; j++) {
            int n = n0 + nt + 16 * j;
            if (n < NG_) {
                float2 p = unpack2(acc[i][j]);
                orow[n] = p.x + p.y + bias[n];
            }
        }
    }
}

// ------------------- kernel 2: clustered LSTM chunk, dataflow sync ---------
// r14 protocol; mm is batch-PAIRED (2 independent acc chains, 2 passes) to fill
// the FFMA2 chain gaps and deepen LDS pipelining within the ~20 free registers.
// red_s parity-buffered -> only ONE __syncthreads per step.
__global__ void __launch_bounds__(RTc, 1) __cluster_dims__(CL, 1, 1)
lstm_chunk(const float* __restrict__ WrF,
           const float* __restrict__ WrB,
           const int* __restrict__ seqlen, int s0) {
    const int bx  = blockIdx.x;          // 0..127
    const int dir = bx >> 6;
    const int bg  = (bx >> 3) & 7;       // 0..7 (4 batches each)
    const int ug  = bx & 7;              // cluster rank
    const float* __restrict__ Wr = dir ? WrB : WrF;
    const int u0  = ug * NUc;
    const int tid = threadIdx.x;

    __shared__ ULL   hh[2][BGc][HPAD];               // h k-pairs: [slot][b][pair]
    __shared__ float red_s[2][KCHc][BGc][NCOLc];     // parity-buffered partials
    __shared__ float c_s[BGc][NUc], h_s[BGc][NUc];
    __shared__ int   seq_s[BGc];
    __shared__ ULL   mbars[CL];                      // per-source-slice mbarriers

    const int kch = tid / NCOLc;         // 0..3
    const int c   = tid % NCOLc;         // 0..151

    const bool gt  = (tid < BGc * NUc);  // 152 gate threads (ALL push; invalid push 0)
    const int  gb_ = tid / NUc, gi_ = tid % NUc;
    const int  gu  = u0 + gi_;
    const bool gv  = gt && (gu < U_);
    const int  gbatch = bg * BGc + gb_;

    // ---- preload Wr slice: w2[j] = (Wr[k0+2j][gc], Wr[k0+2j+1][gc]) ----
    ULL w2[KPc];
    {
        int g = c / NUc, i = c % NUc;
        int u = u0 + i;
        bool v = (u < U_);
        int gc = g * U_ + (v ? u : 0);
        int k0 = kch * (2 * KPc);
#pragma unroll
        for (int j = 0; j < KPc; j++) {
            int k = k0 + 2 * j;
            float a = (v && k     < D_) ? Wr[(size_t)k       * NG_ + gc] : 0.f;
            float b = (v && k + 1 < D_) ? Wr[(size_t)(k + 1) * NG_ + gc] : 0.f;
            w2[j] = pack2(a, b);
        }
    }
    if (tid < BGc) seq_s[tid] = seqlen[bg * BGc + tid];

    const uint32_t mb0 = smem_u32(&mbars[0]);
    const uint32_t myMbar = mb0 + 8u * (uint32_t)ug;     // slice-ug mbar (same offset all CTAs)
    const uint32_t mbarK0 = mb0 + 8u * (uint32_t)(2 * kch);
    const uint32_t mbarK1 = mbarK0 + 8u;

    // ---- init mbars + pre-arm phase 0, seed state ----
    if (tid < CL) {
        mbar_init(mb0 + 8u * tid, 1);
        mbar_arm(mb0 + 8u * tid, SLICE_BYTES);           // phase 0: gates(0) pushes
    }
    for (int x = tid; x < 2 * BGc * HPAD; x += RTc) ((ULL*)hh)[x] = 0ULL;
    __syncthreads();
    for (int x = tid; x < BGc * 150; x += RTc) {
        int b = x / 150, jp = x % 150;
        const float* hsrc = &g_hcur[dir][bg * BGc + b][0];
        hh[0][b][jp] = pack2(hsrc[2 * jp], hsrc[2 * jp + 1]);
    }
    if (gt) {
        c_s[gb_][gi_] = gv ? g_ccur[dir][gbatch][gu] : 0.f;
        h_s[gb_][gi_] = gv ? g_hcur[dir][gbatch][gu] : 0.f;
    }
    __syncthreads();
    cluster_sync_();   // mbars + seeds visible before any peer st.async

    uint32_t slotA = 0;
    if (gt) slotA = smem_u32(&hh[0][gb_][gu >> 1]) + (gu & 1) * 4;
    const uint32_t slotStride = (uint32_t)(BGc * HPAD * 8);

    for (int sl = 0; sl < CSTEPS; sl++) {
        const int s = s0 + sl;
        const int t = dir ? (T_ - 1 - s) : s;
        const int p = sl & 1;

        // ---- prefetch zx row for this step ----
        float zpre[4];
        if (gv) {
            const float* zrow = &g_zx[dir][gbatch * T_ + t][0];
#pragma unroll
            for (int g = 0; g < 4; g++) zpre[g] = __ldcg(zrow + g * U_ + gu);
        }

        // ---- wait this k-chunk's two source slices (phase sl-1), re-arm ----
        if (sl > 0) {
            const uint32_t par = (uint32_t)((sl - 1) & 1);
            mbar_wait(mbarK0, par);
            mbar_wait(mbarK1, par);
            if (sl <= CSTEPS - 2) {           // arm phase sl (consumed at sl+1)
                if (c == 0) mbar_arm(mbarK0, SLICE_BYTES);
                if (c == 1) mbar_arm(mbarK1, SLICE_BYTES);
            }
        }

        // ---- matmul: batch-PAIRED (2 indep chains per pass, 2 passes) ----
#pragma unroll
        for (int bp = 0; bp < 2; bp++) {
            const ulonglong2* h0 = (const ulonglong2*)&hh[p][2 * bp][kch * KPc];
            const ulonglong2* h1 = (const ulonglong2*)&hh[p][2 * bp + 1][kch * KPc];
            ULL a0 = 0ULL, a1 = 0ULL;
#pragma unroll
            for (int jj = 0; jj < KPc / 2; jj++) {
                ulonglong2 v0 = h0[jj];
                ulonglong2 v1 = h1[jj];
                ffma2(a0, w2[2 * jj],     v0.x);
                ffma2(a1, w2[2 * jj],     v1.x);
                ffma2(a0, w2[2 * jj + 1], v0.y);
                ffma2(a1, w2[2 * jj + 1], v1.y);
            }
            float2 p0 = unpack2(a0), p1 = unpack2(a1);
            red_s[p][kch][2 * bp][c]     = p0.x + p0.y;
            red_s[p][kch][2 * bp + 1][c] = p1.x + p1.y;
        }
        __syncthreads();   // the ONE per-step CTA barrier (red_s ready for gates)

        // ---- gates + state update + st.async push ----
        if (gt) {
            float hw = 0.f;
            if (gv) {
                float z[4];
#pragma unroll
                for (int g = 0; g < 4; g++) {
                    int cc = g * NUc + gi_;
                    z[g] = zpre[g] + red_s[p][0][gb_][cc] + red_s[p][1][gb_][cc]
                                   + red_s[p][2][gb_][cc] + red_s[p][3][gb_][cc];
                }
                float ig = sigm_f(z[0]), fg = sigm_f(z[1]);
                float gg = tanh_f(z[2]), og = sigm_f(z[3]);
                float c_old = c_s[gb_][gi_], h_old = h_s[gb_][gi_];
                float c_new = fg * c_old + ig * gg;
                float h_new = og * tanh_f(c_new);
                bool  mk = (t < seq_s[gb_]);
                hw       = mk ? h_new : h_old;
                float cw = mk ? c_new : c_old;
                c_s[gb_][gi_] = cw;
                h_s[gb_][gi_] = hw;
                g_hs[dir][gbatch][t][gu] = hw;       // history for fc
                if (sl == CSTEPS - 1) {              // carry state to next chunk
                    g_hcur[dir][gbatch][gu] = hw;
                    g_ccur[dir][gbatch][gu] = cw;
                }
            }
            if (sl < CSTEPS - 1) {
                // push into all 8 CTAs' next slot; completes their mbar[ug]
                uint32_t a0 = slotA + (uint32_t)(p ^ 1) * slotStride;
#pragma unroll
                for (int r = 0; r < CL; r++) st_async_f32(a0, myMbar, r, hw);
            }
        }
        // no trailing __syncthreads: red_s parity + mbar waits order reuse
    }
    cluster_sync_();       // no CTA exits while peers' st.async may target it
}

// ------------------- kernel 3: out = [h_fwd|h_bwd] @ fc_W + fc_b -----------
__global__ void __launch_bounds__(256) fc_kernel(const float* __restrict__ fcW,
                                                 const float* __restrict__ fcb,
                                                 float* __restrict__ out) {
    __shared__ float Ws[1803];
    const int tid = threadIdx.x;
    for (int x = tid; x < 1800; x += 256) Ws[x] = fcW[x];
    if (tid < 3) Ws[1800 + tid] = fcb[tid];
    __syncthreads();

    const int wid = tid >> 5, lane = tid & 31;
    const int r = blockIdx.x * 8 + wid;       // 0..16383
    const int b = r >> 9, t = r & 511;
    float a0 = 0.f, a1 = 0.f, a2 = 0.f;
    const float* hf = &g_hs[0][b][t][0];
    const float* hb = &g_hs[1][b][t][0];
    for (int k = lane; k < U_; k += 32) {
        float v = hf[k];
        a0 += v * Ws[k * 3];  a1 += v * Ws[k * 3 + 1];  a2 += v * Ws[k * 3 + 2];
        float w = hb[k];
        a0 += w * Ws[(U_ + k) * 3];  a1 += w * Ws[(U_ + k) * 3 + 1];  a2 += w * Ws[(U_ + k) * 3 + 2];
    }
#pragma unroll
    for (int off = 16; off; off >>= 1) {
        a0 += __shfl_down_sync(0xffffffffu, a0, off);
        a1 += __shfl_down_sync(0xffffffffu, a1, off);
        a2 += __shfl_down_sync(0xffffffffu, a2, off);
    }
    if (lane == 0) {
        out[r * 3 + 0] = a0 + Ws[1800];
        out[r * 3 + 1] = a1 + Ws[1801];
        out[r * 3 + 2] = a2 + Ws[1802];
    }
}

// ------------------- launch ------------------------------------------------
extern "C" void kernel_launch(void* const* d_in, const int* in_sizes, int n_in,
                              void* d_out, int out_size) {
    const int*   inputs = (const int*)d_in[0];
    const int*   seqlen = (const int*)d_in[1];
    const float* emb    = (const float*)d_in[2];
    const float* Wk_f   = (const float*)d_in[3];
    const float* Wr_f   = (const float*)d_in[4];
    const float* b_f    = (const float*)d_in[5];
    const float* Wk_b   = (const float*)d_in[6];
    const float* Wr_b   = (const float*)d_in[7];
    const float* b_b    = (const float*)d_in[8];
    const float* fc_W   = (const float*)d_in[9];
    const float* fc_b   = (const float*)d_in[10];
    float* out = (float*)d_out;

    init_state<<<(2 * B_ * U_ + 255) / 256, 256>>>();
    gemm_zx<<<dim3(128, 19, 2), 256>>>(inputs, Wk_f, Wk_b, b_f, b_b, emb);
    for (int ch = 0; ch < T_ / CSTEPS; ch++)
        lstm_chunk<<<128, RTc>>>(Wr_f, Wr_b, seqlen, ch * CSTEPS);
    fc_kernel<<<2048, 256>>>(fc_W, fc_b, out);
}

// round 16
// speedup vs baseline: 1.0714x; 1.0714x over previous
#include <cuda_runtime.h>
#include <cuda_bf16.h>
#include <cstdint>
#include <math.h>

#define B_    32
#define T_    512
#define D_    300
#define U_    300
#define NG_   1200       // 4*U
#define ZPAD  1216       // padded zx row stride
#define M_    16384      // B*T

// ---- clustered recurrence tiling ----
#define CL    8          // CTAs per cluster (unit groups)
#define NUc   38         // units per CTA (8*38=304, last 4 masked)
#define NCOLc 152        // 4*NUc gate columns per CTA
#define BGc   4          // batches per CTA
#define KCHc  4          // k chunks
#define KPc   38         // k-pairs per chunk (4*76 = 304 padded k)
#define GRPT  160        // threads per k-chunk group (warp-aligned)
#define RTc   640        // 20 warps = 4 groups x 160
#define CSTEPS 128       // steps per chunk launch (4 chunks x 128 = 512)
#define SLICE_BYTES 640u // bulk payload per source slice (4 b x 160B padded)
#define SLOT_OFF 5120u   // hh slot stride in bytes (CL*BGc*20*8)

typedef unsigned long long ULL;

// ------------------- static device scratch (no allocs allowed) -------------
__device__ __align__(16) float g_zx[2][M_][ZPAD];     // x@Wk+b per dir
__device__ __align__(16) float g_hs[2][B_][T_][U_];   // h history per dir
__device__ __align__(16) float g_hcur[2][B_][U_];     // h carried across chunks
__device__ __align__(16) float g_ccur[2][B_][U_];     // c carried across chunks

// ------------------- helpers ----------------------------------------------
union UF2 { float2 f; ULL u; };
__device__ __forceinline__ ULL pack2(float a, float b) {
    UF2 x; x.f = make_float2(a, b); return x.u;
}
__device__ __forceinline__ float2 unpack2(ULL v) {
    UF2 x; x.u = v; return x.f;
}
__device__ __forceinline__ void ffma2(ULL& d, ULL a, ULL b) {
    asm("fma.rn.f32x2 %0, %1, %2, %0;" : "+l"(d) : "l"(a), "l"(b));
}
__device__ __forceinline__ float sigm_f(float x) {
    return __fdividef(1.f, 1.f + __expf(-x));
}
__device__ __forceinline__ float tanh_f(float x) {
    float e = __expf(2.f * fabsf(x));
    float t = 1.f - __fdividef(2.f, e + 1.f);
    return copysignf(t, x);
}
__device__ __forceinline__ uint32_t smem_u32(const void* p) {
    uint32_t a;
    asm("{ .reg .u64 t; cvta.to.shared.u64 t, %1; cvt.u32.u64 %0, t; }" : "=r"(a) : "l"(p));
    return a;
}
__device__ __forceinline__ uint32_t mapa_u32(uint32_t laddr, int rank) {
    uint32_t ra;
    asm("mapa.shared::cluster.u32 %0, %1, %2;" : "=r"(ra) : "r"(laddr), "r"(rank));
    return ra;
}
__device__ __forceinline__ void mbar_init(uint32_t mbar, uint32_t cnt) {
    asm volatile("mbarrier.init.shared.b64 [%0], %1;" :: "r"(mbar), "r"(cnt) : "memory");
}
__device__ __forceinline__ void mbar_arm(uint32_t mbar, uint32_t txb) {
    asm volatile("mbarrier.arrive.expect_tx.shared.b64 _, [%0], %1;" :: "r"(mbar), "r"(txb) : "memory");
}
__device__ __forceinline__ void mbar_wait(uint32_t mbar, uint32_t parity) {
    asm volatile(
        "{\n\t.reg .pred P;\n\t"
        "W_%=:\n\t"
        "mbarrier.try_wait.parity.acquire.cta.shared::cta.b64 P, [%0], %1, 0x989680;\n\t"
        "@!P bra W_%=;\n\t}"
        :: "r"(mbar), "r"(parity) : "memory");
}
__device__ __forceinline__ void bulk_push(uint32_t dst, uint32_t src, uint32_t bytes,
                                          uint32_t rembar) {
    asm volatile(
        "cp.async.bulk.shared::cluster.shared::cta.mbarrier::complete_tx::bytes "
        "[%0], [%1], %2, [%3];"
        :: "r"(dst), "r"(src), "r"(bytes), "r"(rembar) : "memory");
}
__device__ __forceinline__ void cluster_sync_() {
    asm volatile("barrier.cluster.arrive.aligned;" ::: "memory");
    asm volatile("barrier.cluster.wait.aligned;" ::: "memory");
}

// ------------------- kernel 0: zero carried state --------------------------
__global__ void init_state() {
    int i = blockIdx.x * blockDim.x + threadIdx.x;
    if (i < 2 * B_ * U_) {
        ((float*)g_hcur)[i] = 0.f;
        ((float*)g_ccur)[i] = 0.f;
    }
}

// ------------------- kernel 1: zx = gather(emb) @ Wk + b -------------------
#define GKT 19   // ceil(304/16)

__global__ void __launch_bounds__(256, 2) gemm_zx(const int* __restrict__ idx,
                                                  const float* __restrict__ WkF,
                                                  const float* __restrict__ WkB,
                                                  const float* __restrict__ bF,
                                                  const float* __restrict__ bB,
                                                  const float* __restrict__ emb) {
    const int dir = blockIdx.z;
    const float* __restrict__ Wk   = dir ? WkB : WkF;
    const float* __restrict__ bias = dir ? bB  : bF;
    const int m0 = blockIdx.x * 128;
    const int n0 = blockIdx.y * 64;
    const int tid = threadIdx.x;

    __shared__ ULL A_s[2][128][9];
    __shared__ ULL B_s[2][64][9];
    __shared__ int row_s[128];

    if (tid < 128) row_s[tid] = idx[m0 + tid];
    __syncthreads();

    const int mt = tid >> 4;
    const int nt = tid & 15;

    ULL acc[8][4];
#pragma unroll
    for (int i = 0; i < 8; i++)
#pragma unroll
        for (int j = 0; j < 4; j++) acc[i][j] = 0ULL;

    ULL aReg[4];
    ULL bReg[2];

    auto grab = [&](int kt) {
#pragma unroll
        for (int l = 0; l < 4; l++) {
            int id = tid + 256 * l;
            int m  = id >> 3;
            int kp = id & 7;
            int k0 = kt * 16 + kp * 2;
            if (k0 < D_) {
                const float* ep = emb + (size_t)row_s[m] * D_ + k0;
                float2 v = *(const float2*)ep;
                aReg[l] = pack2(v.x, v.y);
            } else aReg[l] = 0ULL;
        }
#pragma unroll
        for (int l = 0; l < 2; l++) {
            int id = tid + 256 * l;
            int n  = id & 63;
            int kp = id >> 6;
            int k0 = kt * 16 + kp * 2;
            int gn = n0 + n;
            if (k0 < D_ && gn < NG_) {
                float v0 = Wk[(size_t)k0 * NG_ + gn];
                float v1 = Wk[(size_t)(k0 + 1) * NG_ + gn];
                bReg[l] = pack2(v0, v1);
            } else bReg[l] = 0ULL;
        }
    };
    auto commit = [&](int st) {
#pragma unroll
        for (int l = 0; l < 4; l++) {
            int id = tid + 256 * l;
            A_s[st][id >> 3][id & 7] = aReg[l];
        }
#pragma unroll
        for (int l = 0; l < 2; l++) {
            int id = tid + 256 * l;
            B_s[st][id & 63][id >> 6] = bReg[l];
        }
    };

    grab(0); commit(0);
    __syncthreads();

    for (int kt = 0; kt < GKT; kt++) {
        const int st = kt & 1;
        if (kt + 1 < GKT) grab(kt + 1);

#pragma unroll
        for (int kp = 0; kp < 8; kp++) {
            ULL a2[8], b2[4];
#pragma unroll
            for (int i = 0; i < 8; i++) a2[i] = A_s[st][mt + 16 * i][kp];
#pragma unroll
            for (int j = 0; j < 4; j++) b2[j] = B_s[st][nt + 16 * j][kp];
#pragma unroll
            for (int i = 0; i < 8; i++)
#pragma unroll
                for (int j = 0; j < 4; j++) ffma2(acc[i][j], a2[i], b2[j]);
        }

        if (kt + 1 < GKT) commit((kt + 1) & 1);
        __syncthreads();
    }

#pragma unroll
    for (int i = 0; i < 8; i++) {
        int m = m0 + mt + 16 * i;
        float* orow = &g_zx[dir][m][0];
#pragma unroll
        for (int j = 0; j < 4; j++) {
            int n = n0 + nt + 16 * j;
            if (n < NG_) {
                float2 p = unpack2(acc[i][j]);
                orow[n] = p.x + p.y + bias[n];
            }
        }
    }
}

// ------------------- kernel 2: clustered LSTM chunk, BULK dataflow ---------
// r14 protocol, but h pushed as ONE 640B cp.async.bulk per peer (8 msgs/step)
// instead of 1216 scalar st.async messages. hh: [slot][src][b][20 ULL pairs].
__global__ void __launch_bounds__(RTc, 1) __cluster_dims__(CL, 1, 1)
lstm_chunk(const float* __restrict__ WrF,
           const float* __restrict__ WrB,
           const int* __restrict__ seqlen, int s0) {
    const int bx  = blockIdx.x;          // 0..127
    const int dir = bx >> 6;
    const int bg  = (bx >> 3) & 7;       // 0..7 (4 batches each)
    const int ug  = bx & 7;              // cluster rank
    const float* __restrict__ Wr = dir ? WrB : WrF;
    const int u0  = ug * NUc;
    const int tid = threadIdx.x;

    __shared__ __align__(16) ULL   hh[2][CL][BGc][20];    // h pairs, 640B/src slice
    __shared__ __align__(16) float stageF[2][BGc][40];    // outgoing slice staging
    __shared__ float red_s[KCHc][BGc][NCOLc];
    __shared__ float c_s[BGc][NUc], h_s[BGc][NUc];
    __shared__ int   seq_s[BGc];
    __shared__ ULL   mbars[CL];                           // per-source-slice mbars

    const int  kch = tid / GRPT;          // 0..3 (warp-uniform)
    const int  c   = tid % GRPT;          // 0..159
    const bool mmA = (c < NCOLc);         // 152 active mm lanes per group

    const bool gt  = (tid < BGc * NUc);   // 152 gate threads (in group 0)
    const int  gb_ = tid / NUc, gi_ = tid % NUc;
    const int  gu  = u0 + gi_;
    const bool gv  = gt && (gu < U_);
    const int  gbatch = bg * BGc + gb_;

    // ---- preload Wr slice: w2[j] = (Wr[k0+2j][gc], Wr[k0+2j+1][gc]) ----
    ULL w2[KPc];
    if (mmA) {
        int g = c / NUc, i = c % NUc;
        int u = u0 + i;
        bool v = (u < U_);
        int gc = g * U_ + (v ? u : 0);
        int k0 = kch * (2 * KPc);
#pragma unroll
        for (int j = 0; j < KPc; j++) {
            int k = k0 + 2 * j;
            float a = (v && k     < D_) ? Wr[(size_t)k       * NG_ + gc] : 0.f;
            float b = (v && k + 1 < D_) ? Wr[(size_t)(k + 1) * NG_ + gc] : 0.f;
            w2[j] = pack2(a, b);
        }
    }
    if (tid < BGc) seq_s[tid] = seqlen[bg * BGc + tid];

    const uint32_t mb0 = smem_u32(&mbars[0]);
    const uint32_t mbarK0 = mb0 + 8u * (uint32_t)(2 * kch);
    const uint32_t mbarK1 = mbarK0 + 8u;

    // ---- init mbars + pre-arm phase 0, zero+seed state ----
    if (tid < CL) {
        mbar_init(mb0 + 8u * tid, 1);
        mbar_arm(mb0 + 8u * tid, SLICE_BYTES);            // phase 0: pushes(0)
    }
    for (int x = tid; x < 2 * CL * BGc * 20; x += RTc) ((ULL*)hh)[x] = 0ULL;
    for (int x = tid; x < 2 * BGc * 40; x += RTc) ((float*)stageF)[x] = 0.f;
    __syncthreads();
    for (int x = tid; x < CL * BGc * 19; x += RTc) {
        int src = x / (BGc * 19);
        int rem = x % (BGc * 19);
        int b = rem / 19, jp = rem % 19;
        int u = src * NUc + 2 * jp;
        const float* hsrc = &g_hcur[dir][bg * BGc + b][0];
        float f0 = (u     < U_) ? hsrc[u]     : 0.f;
        float f1 = (u + 1 < U_) ? hsrc[u + 1] : 0.f;
        hh[0][src][b][jp] = pack2(f0, f1);
    }
    if (gt) {
        c_s[gb_][gi_] = gv ? g_ccur[dir][gbatch][gu] : 0.f;
        h_s[gb_][gi_] = gv ? g_hcur[dir][gbatch][gu] : 0.f;
    }
    __syncthreads();
    cluster_sync_();   // mbars + seeds visible before any peer bulk

    // ---- hoisted per-rank remote addresses (tid<8 are the pushers) ----
    uint32_t dstBase = 0, rembar = 0;
    const uint32_t stageBase = smem_u32(&stageF[0][0][0]);
    if (tid < CL) {
        dstBase = mapa_u32(smem_u32(&hh[0][ug][0][0]), tid);   // our slice @ rank tid
        rembar  = mapa_u32(mb0 + 8u * (uint32_t)ug, tid);      // their mbars[our ug]
    }

    for (int sl = 0; sl < CSTEPS; sl++) {
        const int s = s0 + sl;
        const int t = dir ? (T_ - 1 - s) : s;
        const int p = sl & 1;

        // ---- prefetch zx row for this step ----
        float zpre[4];
        if (gv) {
            const float* zrow = &g_zx[dir][gbatch * T_ + t][0];
#pragma unroll
            for (int g = 0; g < 4; g++) zpre[g] = __ldcg(zrow + g * U_ + gu);
        }

        // ---- wait this k-chunk's two source slices (phase sl-1), re-arm ----
        if (sl > 0) {
            const uint32_t par = (uint32_t)((sl - 1) & 1);
            mbar_wait(mbarK0, par);
            mbar_wait(mbarK1, par);
            if (sl <= CSTEPS - 2) {            // arm phase sl (consumed at sl+1)
                if (c == 0) mbar_arm(mbarK0, SLICE_BYTES);
                if (c == 1) mbar_arm(mbarK1, SLICE_BYTES);
            }
        }

        // ---- matmul: per batch, 2 padded src slices of 19 pairs ----
        if (mmA) {
#pragma unroll
            for (int b = 0; b < BGc; b++) {
                const ULL* h0 = &hh[p][2 * kch][b][0];
                const ULL* h1 = &hh[p][2 * kch + 1][b][0];
                ULL acc = 0ULL;
#pragma unroll
                for (int jj = 0; jj < 9; jj++) {
                    ulonglong2 v = *(const ulonglong2*)&h0[2 * jj];
                    ffma2(acc, w2[2 * jj],     v.x);
                    ffma2(acc, w2[2 * jj + 1], v.y);
                }
                ffma2(acc, w2[18], h0[18]);
#pragma unroll
                for (int jj = 0; jj < 9; jj++) {
                    ulonglong2 v = *(const ulonglong2*)&h1[2 * jj];
                    ffma2(acc, w2[19 + 2 * jj], v.x);
                    ffma2(acc, w2[20 + 2 * jj], v.y);
                }
                ffma2(acc, w2[37], h1[18]);
                float2 pr = unpack2(acc);
                red_s[kch][b][c] = pr.x + pr.y;
            }
        }
        __syncthreads();

        // ---- gates + state update; write outgoing slice to staging ----
        if (gt) {
            float hw = 0.f;
            if (gv) {
                float z[4];
#pragma unroll
                for (int g = 0; g < 4; g++) {
                    int cc = g * NUc + gi_;
                    z[g] = zpre[g] + red_s[0][gb_][cc] + red_s[1][gb_][cc]
                                   + red_s[2][gb_][cc] + red_s[3][gb_][cc];
                }
                float ig = sigm_f(z[0]), fg = sigm_f(z[1]);
                float gg = tanh_f(z[2]), og = sigm_f(z[3]);
                float c_old = c_s[gb_][gi_], h_old = h_s[gb_][gi_];
                float c_new = fg * c_old + ig * gg;
                float h_new = og * tanh_f(c_new);
                bool  mk = (t < seq_s[gb_]);
                hw       = mk ? h_new : h_old;
                float cw = mk ? c_new : c_old;
                c_s[gb_][gi_] = cw;
                h_s[gb_][gi_] = hw;
                g_hs[dir][gbatch][t][gu] = hw;        // history for fc
                if (sl == CSTEPS - 1) {               // carry state to next chunk
                    g_hcur[dir][gbatch][gu] = hw;
                    g_ccur[dir][gbatch][gu] = cw;
                }
            }
            stageF[p ^ 1][gb_][gi_] = hw;             // pads [38..39] stay 0
        }
        __syncthreads();                               // staging complete

        // ---- ONE bulk per peer: 640B slice + remote mbar completion ----
        if (sl < CSTEPS - 1 && tid < CL) {
            asm volatile("fence.proxy.async.shared::cta;" ::: "memory");
            uint32_t dst = dstBase + (uint32_t)(p ^ 1) * SLOT_OFF;
            uint32_t src = stageBase + (uint32_t)(p ^ 1) * SLICE_BYTES;
            bulk_push(dst, src, SLICE_BYTES, rembar);
        }
    }
    cluster_sync_();       // no CTA exits while peers' bulks may target it
}

// ------------------- kernel 3: out = [h_fwd|h_bwd] @ fc_W + fc_b -----------
__global__ void __launch_bounds__(256) fc_kernel(const float* __restrict__ fcW,
                                                 const float* __restrict__ fcb,
                                                 float* __restrict__ out) {
    __shared__ float Ws[1803];
    const int tid = threadIdx.x;
    for (int x = tid; x < 1800; x += 256) Ws[x] = fcW[x];
    if (tid < 3) Ws[1800 + tid] = fcb[tid];
    __syncthreads();

    const int wid = tid >> 5, lane = tid & 31;
    const int r = blockIdx.x * 8 + wid;       // 0..16383
    const int b = r >> 9, t = r & 511;
    float a0 = 0.f, a1 = 0.f, a2 = 0.f;
    const float* hf = &g_hs[0][b][t][0];
    const float* hb = &g_hs[1][b][t][0];
    for (int k = lane; k < U_; k += 32) {
        float v = hf[k];
        a0 += v * Ws[k * 3];  a1 += v * Ws[k * 3 + 1];  a2 += v * Ws[k * 3 + 2];
        float w = hb[k];
        a0 += w * Ws[(U_ + k) * 3];  a1 += w * Ws[(U_ + k) * 3 + 1];  a2 += w * Ws[(U_ + k) * 3 + 2];
    }
#pragma unroll
    for (int off = 16; off; off >>= 1) {
        a0 += __shfl_down_sync(0xffffffffu, a0, off);
        a1 += __shfl_down_sync(0xffffffffu, a1, off);
        a2 += __shfl_down_sync(0xffffffffu, a2, off);
    }
    if (lane == 0) {
        out[r * 3 + 0] = a0 + Ws[1800];
        out[r * 3 + 1] = a1 + Ws[1801];
        out[r * 3 + 2] = a2 + Ws[1802];
    }
}

// ------------------- launch ------------------------------------------------
extern "C" void kernel_launch(void* const* d_in, const int* in_sizes, int n_in,
                              void* d_out, int out_size) {
    const int*   inputs = (const int*)d_in[0];
    const int*   seqlen = (const int*)d_in[1];
    const float* emb    = (const float*)d_in[2];
    const float* Wk_f   = (const float*)d_in[3];
    const float* Wr_f   = (const float*)d_in[4];
    const float* b_f    = (const float*)d_in[5];
    const float* Wk_b   = (const float*)d_in[6];
    const float* Wr_b   = (const float*)d_in[7];
    const float* b_b    = (const float*)d_in[8];
    const float* fc_W   = (const float*)d_in[9];
    const float* fc_b   = (const float*)d_in[10];
    float* out = (float*)d_out;

    init_state<<<(2 * B_ * U_ + 255) / 256, 256>>>();
    gemm_zx<<<dim3(128, 19, 2), 256>>>(inputs, Wk_f, Wk_b, b_f, b_b, emb);
    for (int ch = 0; ch < T_ / CSTEPS; ch++)
        lstm_chunk<<<128, RTc>>>(Wr_f, Wr_b, seqlen, ch * CSTEPS);
    fc_kernel<<<2048, 256>>>(fc_W, fc_b, out);
}

// round 17
// speedup vs baseline: 1.1896x; 1.1103x over previous
#include <cuda_runtime.h>
#include <cuda_bf16.h>
#include <cstdint>
#include <math.h>

#define B_    32
#define T_    512
#define D_    300
#define U_    300
#define NG_   1200       // 4*U
#define ZPAD  1216       // padded zx row stride
#define M_    16384      // B*T

// ---- clustered recurrence tiling (r14 compute config) ----
#define CL    8          // CTAs per cluster (unit groups)
#define NUc   38         // units per CTA (8*38=304, last 4 masked)
#define NCOLc 152        // 4*NUc gate columns per CTA
#define BGc   4          // batches per CTA
#define KCHc  4          // k chunks
#define KPc   38         // k-pairs per chunk (4*76 = 304 padded k)
#define HPAD  154        // hh row length in ULL pairs (152 used + pad)
#define RTc   608        // threads = KCHc * NCOLc exactly
#define CSTEPS 128       // steps per chunk launch (4 chunks x 128 = 512)
#define SLICE_BYTES 608u // 152 pushed f32 per source slice
#define ZLOOK 3          // zx ring lookahead (4 slots)

typedef unsigned long long ULL;

// ------------------- static device scratch (no allocs allowed) -------------
__device__ __align__(16) float g_zx[2][M_][ZPAD];     // x@Wk+b per dir
__device__ __align__(16) float g_hs[2][B_][T_][U_];   // h history per dir
__device__ __align__(16) float g_hcur[2][B_][U_];     // h carried across chunks
__device__ __align__(16) float g_ccur[2][B_][U_];     // c carried across chunks

// ------------------- helpers ----------------------------------------------
union UF2 { float2 f; ULL u; };
__device__ __forceinline__ ULL pack2(float a, float b) {
    UF2 x; x.f = make_float2(a, b); return x.u;
}
__device__ __forceinline__ float2 unpack2(ULL v) {
    UF2 x; x.u = v; return x.f;
}
__device__ __forceinline__ void ffma2(ULL& d, ULL a, ULL b) {
    asm("fma.rn.f32x2 %0, %1, %2, %0;" : "+l"(d) : "l"(a), "l"(b));
}
__device__ __forceinline__ float sigm_f(float x) {
    return __fdividef(1.f, 1.f + __expf(-x));
}
__device__ __forceinline__ float tanh_f(float x) {
    float e = __expf(2.f * fabsf(x));
    float t = 1.f - __fdividef(2.f, e + 1.f);
    return copysignf(t, x);
}
__device__ __forceinline__ uint32_t smem_u32(const void* p) {
    uint32_t a;
    asm("{ .reg .u64 t; cvta.to.shared.u64 t, %1; cvt.u32.u64 %0, t; }" : "=r"(a) : "l"(p));
    return a;
}
// store+remote-mbar-completion in one message (no fences needed)
__device__ __forceinline__ void st_async_f32(uint32_t laddr, uint32_t lmbar, int rank, float v) {
    uint32_t ra, rm;
    asm volatile("mapa.shared::cluster.u32 %0, %1, %2;" : "=r"(ra) : "r"(laddr), "r"(rank));
    asm volatile("mapa.shared::cluster.u32 %0, %1, %2;" : "=r"(rm) : "r"(lmbar), "r"(rank));
    asm volatile("st.async.weak.shared::cluster.mbarrier::complete_tx::bytes.u32 [%0], %1, [%2];"
                 :: "r"(ra), "r"(__float_as_uint(v)), "r"(rm) : "memory");
}
__device__ __forceinline__ void mbar_init(uint32_t mbar, uint32_t cnt) {
    asm volatile("mbarrier.init.shared.b64 [%0], %1;" :: "r"(mbar), "r"(cnt) : "memory");
}
__device__ __forceinline__ void mbar_arm(uint32_t mbar, uint32_t txb) {
    asm volatile("mbarrier.arrive.expect_tx.shared.b64 _, [%0], %1;" :: "r"(mbar), "r"(txb) : "memory");
}
__device__ __forceinline__ void mbar_wait(uint32_t mbar, uint32_t parity) {
    asm volatile(
        "{\n\t.reg .pred P;\n\t"
        "W_%=:\n\t"
        "mbarrier.try_wait.parity.acquire.cta.shared::cta.b64 P, [%0], %1, 0x989680;\n\t"
        "@!P bra W_%=;\n\t}"
        :: "r"(mbar), "r"(parity) : "memory");
}
__device__ __forceinline__ void cluster_sync_() {
    asm volatile("barrier.cluster.arrive.aligned;" ::: "memory");
    asm volatile("barrier.cluster.wait.aligned;" ::: "memory");
}
#define CP_ASYNC8(dst, src) \
    asm volatile("cp.async.ca.shared.global [%0], [%1], 8;" :: "r"(dst), "l"(src) : "memory")
#define CP_COMMIT()  asm volatile("cp.async.commit_group;" ::: "memory")
#define CP_WAIT3()   asm volatile("cp.async.wait_group 3;" ::: "memory")

// ------------------- kernel 0: zero carried state --------------------------
__global__ void init_state() {
    int i = blockIdx.x * blockDim.x + threadIdx.x;
    if (i < 2 * B_ * U_) {
        ((float*)g_hcur)[i] = 0.f;
        ((float*)g_ccur)[i] = 0.f;
    }
}

// ------------------- kernel 1: zx = gather(emb) @ Wk + b -------------------
#define GKT 19   // ceil(304/16)

__global__ void __launch_bounds__(256, 2) gemm_zx(const int* __restrict__ idx,
                                                  const float* __restrict__ WkF,
                                                  const float* __restrict__ WkB,
                                                  const float* __restrict__ bF,
                                                  const float* __restrict__ bB,
                                                  const float* __restrict__ emb) {
    const int dir = blockIdx.z;
    const float* __restrict__ Wk   = dir ? WkB : WkF;
    const float* __restrict__ bias = dir ? bB  : bF;
    const int m0 = blockIdx.x * 128;
    const int n0 = blockIdx.y * 64;
    const int tid = threadIdx.x;

    __shared__ ULL A_s[2][128][9];
    __shared__ ULL B_s[2][64][9];
    __shared__ int row_s[128];

    if (tid < 128) row_s[tid] = idx[m0 + tid];
    __syncthreads();

    const int mt = tid >> 4;
    const int nt = tid & 15;

    ULL acc[8][4];
#pragma unroll
    for (int i = 0; i < 8; i++)
#pragma unroll
        for (int j = 0; j < 4; j++) acc[i][j] = 0ULL;

    ULL aReg[4];
    ULL bReg[2];

    auto grab = [&](int kt) {
#pragma unroll
        for (int l = 0; l < 4; l++) {
            int id = tid + 256 * l;
            int m  = id >> 3;
            int kp = id & 7;
            int k0 = kt * 16 + kp * 2;
            if (k0 < D_) {
                const float* ep = emb + (size_t)row_s[m] * D_ + k0;
                float2 v = *(const float2*)ep;
                aReg[l] = pack2(v.x, v.y);
            } else aReg[l] = 0ULL;
        }
#pragma unroll
        for (int l = 0; l < 2; l++) {
            int id = tid + 256 * l;
            int n  = id & 63;
            int kp = id >> 6;
            int k0 = kt * 16 + kp * 2;
            int gn = n0 + n;
            if (k0 < D_ && gn < NG_) {
                float v0 = Wk[(size_t)k0 * NG_ + gn];
                float v1 = Wk[(size_t)(k0 + 1) * NG_ + gn];
                bReg[l] = pack2(v0, v1);
            } else bReg[l] = 0ULL;
        }
    };
    auto commit = [&](int st) {
#pragma unroll
        for (int l = 0; l < 4; l++) {
            int id = tid + 256 * l;
            A_s[st][id >> 3][id & 7] = aReg[l];
        }
#pragma unroll
        for (int l = 0; l < 2; l++) {
            int id = tid + 256 * l;
            B_s[st][id & 63][id >> 6] = bReg[l];
        }
    };

    grab(0); commit(0);
    __syncthreads();

    for (int kt = 0; kt < GKT; kt++) {
        const int st = kt & 1;
        if (kt + 1 < GKT) grab(kt + 1);

#pragma unroll
        for (int kp = 0; kp < 8; kp++) {
            ULL a2[8], b2[4];
#pragma unroll
            for (int i = 0; i < 8; i++) a2[i] = A_s[st][mt + 16 * i][kp];
#pragma unroll
            for (int j = 0; j < 4; j++) b2[j] = B_s[st][nt + 16 * j][kp];
#pragma unroll
            for (int i = 0; i < 8; i++)
#pragma unroll
                for (int j = 0; j < 4; j++) ffma2(acc[i][j], a2[i], b2[j]);
        }

        if (kt + 1 < GKT) commit((kt + 1) & 1);
        __syncthreads();
    }

#pragma unroll
    for (int i = 0; i < 8; i++) {
        int m = m0 + mt + 16 * i;
        float* orow = &g_zx[dir][m][0];
#pragma unroll
        for (int j = 0; j < 4; j++) {
            int n = n0 + nt + 16 * j;
            if (n < NG_) {
                float2 p = unpack2(acc[i][j]);
                orow[n] = p.x + p.y + bias[n];
            }
        }
    }
}

// ------------------- kernel 2: clustered LSTM chunk (r14 + zx ring) --------
// r14 dataflow protocol unchanged; zx now flows through a 4-slot cp.async smem
// ring with 3-step lookahead so DRAM latency leaves the per-step serial chain.
__global__ void __launch_bounds__(RTc, 1) __cluster_dims__(CL, 1, 1)
lstm_chunk(const float* __restrict__ WrF,
           const float* __restrict__ WrB,
           const int* __restrict__ seqlen, int s0) {
    const int bx  = blockIdx.x;          // 0..127
    const int dir = bx >> 6;
    const int bg  = (bx >> 3) & 7;       // 0..7 (4 batches each)
    const int ug  = bx & 7;              // cluster rank
    const float* __restrict__ Wr = dir ? WrB : WrF;
    const int u0  = ug * NUc;
    const int tid = threadIdx.x;

    __shared__ ULL   hh[2][BGc][HPAD];               // h k-pairs: [slot][b][pair]
    __shared__ float red_s[KCHc][BGc][NCOLc];
    __shared__ float c_s[BGc][NUc], h_s[BGc][NUc];
    __shared__ float zring[4][BGc][4][NUc];          // zx ring: [slot][b][gate][i]
    __shared__ int   seq_s[BGc];
    __shared__ ULL   mbars[CL];                      // per-source-slice mbarriers

    const int kch = tid / NCOLc;         // 0..3
    const int c   = tid % NCOLc;         // 0..151

    const bool gt  = (tid < BGc * NUc);  // 152 gate threads (ALL push; invalid push 0)
    const int  gb_ = tid / NUc, gi_ = tid % NUc;
    const int  gu  = u0 + gi_;
    const bool gv  = gt && (gu < U_);
    const int  gbatch = bg * BGc + gb_;

    // ---- zx ring loader mapping: 304 threads x 8B pairs ----
    const bool zl = (tid < 304);
    int zb = 0, zg = 0, zjp = 0; bool zvalid = false;
    const float* zsrc0 = 0; uint32_t zdst0 = 0;
    if (zl) {
        zb = tid / 76; int r = tid % 76; zg = r / 19; zjp = r % 19;
        int u = u0 + 2 * zjp;
        zvalid = (u < U_);
        if (zvalid) {
            zsrc0 = &g_zx[dir][(bg * BGc + zb) * T_ + 0][zg * U_ + u];
            zdst0 = smem_u32(&zring[0][zb][zg][2 * zjp]);
        }
    }
    const uint32_t zslotB = (uint32_t)(BGc * 4 * NUc * 4);   // 2432 B per slot

    // ---- preload Wr slice: w2[j] = (Wr[k0+2j][gc], Wr[k0+2j+1][gc]) ----
    ULL w2[KPc];
    {
        int g = c / NUc, i = c % NUc;
        int u = u0 + i;
        bool v = (u < U_);
        int gc = g * U_ + (v ? u : 0);
        int k0 = kch * (2 * KPc);
#pragma unroll
        for (int j = 0; j < KPc; j++) {
            int k = k0 + 2 * j;
            float a = (v && k     < D_) ? Wr[(size_t)k       * NG_ + gc] : 0.f;
            float b = (v && k + 1 < D_) ? Wr[(size_t)(k + 1) * NG_ + gc] : 0.f;
            w2[j] = pack2(a, b);
        }
    }
    if (tid < BGc) seq_s[tid] = seqlen[bg * BGc + tid];

    const uint32_t mb0 = smem_u32(&mbars[0]);
    const uint32_t myMbar = mb0 + 8u * (uint32_t)ug;     // slice-ug mbar (same offset all CTAs)
    const uint32_t mbarK0 = mb0 + 8u * (uint32_t)(2 * kch);
    const uint32_t mbarK1 = mbarK0 + 8u;

    // ---- init mbars + pre-arm phase 0, seed state ----
    if (tid < CL) {
        mbar_init(mb0 + 8u * tid, 1);
        mbar_arm(mb0 + 8u * tid, SLICE_BYTES);           // phase 0: gates(0) pushes
    }
    for (int x = tid; x < 2 * BGc * HPAD; x += RTc) ((ULL*)hh)[x] = 0ULL;
    __syncthreads();
    for (int x = tid; x < BGc * 150; x += RTc) {
        int b = x / 150, jp = x % 150;
        const float* hsrc = &g_hcur[dir][bg * BGc + b][0];
        hh[0][b][jp] = pack2(hsrc[2 * jp], hsrc[2 * jp + 1]);
    }
    if (gt) {
        c_s[gb_][gi_] = gv ? g_ccur[dir][gbatch][gu] : 0.f;
        h_s[gb_][gi_] = gv ? g_hcur[dir][gbatch][gu] : 0.f;
    }

    // ---- zx ring prologue: issue slots for sl = 0,1,2 ----
#pragma unroll
    for (int f = 0; f < ZLOOK; f++) {
        if (zl && zvalid) {
            int tf = dir ? (T_ - 1 - (s0 + f)) : (s0 + f);
            CP_ASYNC8(zdst0 + (uint32_t)f * zslotB, zsrc0 + (size_t)tf * ZPAD);
        }
        CP_COMMIT();
    }

    __syncthreads();
    cluster_sync_();   // mbars + seeds visible before any peer st.async

    uint32_t slotA = 0;
    if (gt) slotA = smem_u32(&hh[0][gb_][gu >> 1]) + (gu & 1) * 4;
    const uint32_t slotStride = (uint32_t)(BGc * HPAD * 8);

    for (int sl = 0; sl < CSTEPS; sl++) {
        const int s = s0 + sl;
        const int t = dir ? (T_ - 1 - s) : s;
        const int p = sl & 1;

        // ---- issue zx ring loads for step sl+ZLOOK ----
        {
            int slf = sl + ZLOOK;
            if (slf < CSTEPS && zl && zvalid) {
                int tf = dir ? (T_ - 1 - (s0 + slf)) : (s0 + slf);
                CP_ASYNC8(zdst0 + (uint32_t)(slf & 3) * zslotB, zsrc0 + (size_t)tf * ZPAD);
            }
            CP_COMMIT();
        }

        // ---- wait this k-chunk's two source slices (phase sl-1), re-arm ----
        if (sl > 0) {
            const uint32_t par = (uint32_t)((sl - 1) & 1);
            mbar_wait(mbarK0, par);
            mbar_wait(mbarK1, par);
            if (sl <= CSTEPS - 2) {           // arm phase sl (consumed at sl+1)
                if (c == 0) mbar_arm(mbarK0, SLICE_BYTES);
                if (c == 1) mbar_arm(mbarK1, SLICE_BYTES);
            }
        }

        // ---- matmul: partial z for (kch, col) over 4 batches ----
#pragma unroll
        for (int b = 0; b < BGc; b++) {
            const ulonglong2* hp = (const ulonglong2*)&hh[p][b][kch * KPc];
            ULL acc = 0ULL;
#pragma unroll
            for (int jj = 0; jj < KPc / 2; jj++) {
                ulonglong2 h2 = hp[jj];
                ffma2(acc, w2[2 * jj],     h2.x);
                ffma2(acc, w2[2 * jj + 1], h2.y);
            }
            float2 pr = unpack2(acc);
            red_s[kch][b][c] = pr.x + pr.y;
        }
        CP_WAIT3();        // slot sl landed (this thread's oldest group done)
        __syncthreads();   // red_s + zring slot visible to all

        // ---- gates + state update + st.async push ----
        if (gt) {
            float hw = 0.f;
            if (gv) {
                const float* zp = &zring[sl & 3][gb_][0][gi_];
                float z[4];
#pragma unroll
                for (int g = 0; g < 4; g++) {
                    int cc = g * NUc + gi_;
                    z[g] = zp[g * NUc] + red_s[0][gb_][cc] + red_s[1][gb_][cc]
                                       + red_s[2][gb_][cc] + red_s[3][gb_][cc];
                }
                float ig = sigm_f(z[0]), fg = sigm_f(z[1]);
                float gg = tanh_f(z[2]), og = sigm_f(z[3]);
                float c_old = c_s[gb_][gi_], h_old = h_s[gb_][gi_];
                float c_new = fg * c_old + ig * gg;
                float h_new = og * tanh_f(c_new);
                bool  mk = (t < seq_s[gb_]);
                hw       = mk ? h_new : h_old;
                float cw = mk ? c_new : c_old;
                c_s[gb_][gi_] = cw;
                h_s[gb_][gi_] = hw;
                g_hs[dir][gbatch][t][gu] = hw;       // history for fc
                if (sl == CSTEPS - 1) {              // carry state to next chunk
                    g_hcur[dir][gbatch][gu] = hw;
                    g_ccur[dir][gbatch][gu] = cw;
                }
            }
            if (sl < CSTEPS - 1) {
                // push into all 8 CTAs' next slot; completes their mbar[ug]
                uint32_t a0 = slotA + (uint32_t)(p ^ 1) * slotStride;
#pragma unroll
                for (int r = 0; r < CL; r++) st_async_f32(a0, myMbar, r, hw);
            }
        }
        __syncthreads();   // red_s/zring reads done before next step's writes
    }
    cluster_sync_();       // no CTA exits while peers' st.async may target it
}

// ------------------- kernel 3: out = [h_fwd|h_bwd] @ fc_W + fc_b -----------
__global__ void __launch_bounds__(256) fc_kernel(const float* __restrict__ fcW,
                                                 const float* __restrict__ fcb,
                                                 float* __restrict__ out) {
    __shared__ float Ws[1803];
    const int tid = threadIdx.x;
    for (int x = tid; x < 1800; x += 256) Ws[x] = fcW[x];
    if (tid < 3) Ws[1800 + tid] = fcb[tid];
    __syncthreads();

    const int wid = tid >> 5, lane = tid & 31;
    const int r = blockIdx.x * 8 + wid;       // 0..16383
    const int b = r >> 9, t = r & 511;
    float a0 = 0.f, a1 = 0.f, a2 = 0.f;
    const float* hf = &g_hs[0][b][t][0];
    const float* hb = &g_hs[1][b][t][0];
    for (int k = lane; k < U_; k += 32) {
        float v = hf[k];
        a0 += v * Ws[k * 3];  a1 += v * Ws[k * 3 + 1];  a2 += v * Ws[k * 3 + 2];
        float w = hb[k];
        a0 += w * Ws[(U_ + k) * 3];  a1 += w * Ws[(U_ + k) * 3 + 1];  a2 += w * Ws[(U_ + k) * 3 + 2];
    }
#pragma unroll
    for (int off = 16; off; off >>= 1) {
        a0 += __shfl_down_sync(0xffffffffu, a0, off);
        a1 += __shfl_down_sync(0xffffffffu, a1, off);
        a2 += __shfl_down_sync(0xffffffffu, a2, off);
    }
    if (lane == 0) {
        out[r * 3 + 0] = a0 + Ws[1800];
        out[r * 3 + 1] = a1 + Ws[1801];
        out[r * 3 + 2] = a2 + Ws[1802];
    }
}

// ------------------- launch ------------------------------------------------
extern "C" void kernel_launch(void* const* d_in, const int* in_sizes, int n_in,
                              void* d_out, int out_size) {
    const int*   inputs = (const int*)d_in[0];
    const int*   seqlen = (const int*)d_in[1];
    const float* emb    = (const float*)d_in[2];
    const float* Wk_f   = (const float*)d_in[3];
    const float* Wr_f   = (const float*)d_in[4];
    const float* b_f    = (const float*)d_in[5];
    const float* Wk_b   = (const float*)d_in[6];
    const float* Wr_b   = (const float*)d_in[7];
    const float* b_b    = (const float*)d_in[8];
    const float* fc_W   = (const float*)d_in[9];
    const float* fc_b   = (const float*)d_in[10];
    float* out = (float*)d_out;

    init_state<<<(2 * B_ * U_ + 255) / 256, 256>>>();
    gemm_zx<<<dim3(128, 19, 2), 256>>>(inputs, Wk_f, Wk_b, b_f, b_b, emb);
    for (int ch = 0; ch < T_ / CSTEPS; ch++)
        lstm_chunk<<<128, RTc>>>(Wr_f, Wr_b, seqlen, ch * CSTEPS);
    fc_kernel<<<2048, 256>>>(fc_W, fc_b, out);
}